// round 1
// baseline (speedup 1.0000x reference)
#include <cuda_runtime.h>
#include <math.h>

#define Bb 2
#define Ll 8192
#define Dd 1024
#define Hh 16
#define Nn 64
#define KK 4
#define CHUNK 128
#define NCH (Ll / CHUNK)   // 64
#define DT_MIN 1e-4f
#define DT_MAX 0.1f
#define EPSC 1e-6f

// ---------------- scratch (static __device__, no allocation) ----------------
__device__ float g_xnorm[(size_t)Bb * Ll * Dd];            // 16.7M
__device__ float g_param[(size_t)Bb * Ll * 2 * Hh * Nn];   // 33.5M  (B_t,C_t interleaved)
__device__ float g_delta[(size_t)Bb * Ll * Hh];            // 262K
__device__ float g_xconv[(size_t)Bb * Ll * Dd];
__device__ float g_gate [(size_t)Bb * Ll * Dd];
__device__ float g_ssm  [(size_t)Bb * Ll * Dd];
__device__ float g_mixn [(size_t)Bb * Ll * Dd];
__device__ float g_Aagg [(size_t)Bb * Hh * NCH];
__device__ float g_Bagg [(size_t)Bb * Hh * NCH * Nn];
__device__ float g_entry[(size_t)Bb * Hh * NCH * Nn];

__device__ __forceinline__ float sigmoidf_(float v) { return 1.f / (1.f + expf(-v)); }

// ---------------- kernel 1: rmsnorm + dt projection -> delta ----------------
__global__ __launch_bounds__(256) void rmsnorm_dt_kernel(
    const float* __restrict__ x, const float* __restrict__ norm_w,
    const float* __restrict__ dtW, const float* __restrict__ dtb)
{
    int row = blockIdx.x;                 // 0 .. B*L-1
    int tid = threadIdx.x;
    int lane = tid & 31, w = tid >> 5;
    __shared__ float xs[Dd];
    __shared__ float red[8];

    const float* xr = x + (size_t)row * Dd;
    float ss = 0.f;
    for (int k = tid; k < Dd; k += 256) { float v = xr[k]; xs[k] = v; ss += v * v; }
    #pragma unroll
    for (int o = 16; o; o >>= 1) ss += __shfl_xor_sync(0xffffffffu, ss, o);
    if (lane == 0) red[w] = ss;
    __syncthreads();
    float tot = red[0]+red[1]+red[2]+red[3]+red[4]+red[5]+red[6]+red[7];
    float rstd = rsqrtf(tot / (float)Dd + EPSC);

    for (int k = tid; k < Dd; k += 256) {
        float v = xs[k] * norm_w[k] * rstd;
        xs[k] = v;
        g_xnorm[(size_t)row * Dd + k] = v;
    }
    __syncthreads();

    // dt projection: warp w handles heads w and w+8
    for (int hh = w; hh < Hh; hh += 8) {
        const float* wr = dtW + (size_t)hh * Dd;
        float s = 0.f;
        for (int k = lane; k < Dd; k += 32) s += xs[k] * wr[k];
        #pragma unroll
        for (int o = 16; o; o >>= 1) s += __shfl_xor_sync(0xffffffffu, s, o);
        if (lane == 0) {
            float dtr = s + dtb[hh];
            float dt = DT_MIN + sigmoidf_(dtr) * (DT_MAX - DT_MIN);
            g_delta[(size_t)row * Hh + hh] = expf(-dt);
        }
    }
}

// ---------------- kernel 2: depthwise causal conv (K=4) + silu --------------
__global__ __launch_bounds__(256) void conv_kernel(
    const float* __restrict__ cw, const float* __restrict__ cb)
{
    size_t idx = (size_t)blockIdx.x * 256 + threadIdx.x;
    int d = (int)(idx & (Dd - 1));
    size_t bl = idx >> 10;                // row index b*L + l
    int l = (int)(bl & (Ll - 1));
    float w0 = cw[d*4+0], w1 = cw[d*4+1], w2 = cw[d*4+2], w3 = cw[d*4+3];
    float acc = cb[d];
    if (l >= 3) acc += w0 * g_xnorm[(bl - 3) * Dd + d];
    if (l >= 2) acc += w1 * g_xnorm[(bl - 2) * Dd + d];
    if (l >= 1) acc += w2 * g_xnorm[(bl - 1) * Dd + d];
    acc += w3 * g_xnorm[bl * Dd + d];
    g_xconv[idx] = acc / (1.f + expf(-acc));   // silu
}

// ---------------- SIMT fp32 GEMM: C = A(MxK) * W(NxK)^T + bias  -------------
// EPI: 0 = bias only, 1 = sigmoid(bias+..), 2 = + residual
template<int EPI>
__global__ __launch_bounds__(256) void sgemm_k(
    const float* __restrict__ A, const float* __restrict__ W,
    const float* __restrict__ bias, const float* __restrict__ res,
    float* __restrict__ C, int M, int N, int K)
{
    __shared__ float As[8][128];
    __shared__ float Bs[8][128];
    const int tid = threadIdx.x;
    const int bm = blockIdx.y, bn = blockIdx.x;
    const int ty = tid / 16, tx = tid % 16;
    const int loadRow = tid >> 1;          // 0..127
    const int loadCol = (tid & 1) * 4;     // 0 or 4

    const float* Ag = A + ((size_t)bm * 128 + loadRow) * K + loadCol;
    const float* Wg = W + ((size_t)bn * 128 + loadRow) * K + loadCol;

    float acc[8][8];
    #pragma unroll
    for (int i = 0; i < 8; i++)
        #pragma unroll
        for (int j = 0; j < 8; j++) acc[i][j] = 0.f;

    for (int k0 = 0; k0 < K; k0 += 8) {
        float4 av = *(const float4*)(Ag + k0);
        float4 wv = *(const float4*)(Wg + k0);
        As[loadCol+0][loadRow] = av.x;
        As[loadCol+1][loadRow] = av.y;
        As[loadCol+2][loadRow] = av.z;
        As[loadCol+3][loadRow] = av.w;
        Bs[loadCol+0][loadRow] = wv.x;
        Bs[loadCol+1][loadRow] = wv.y;
        Bs[loadCol+2][loadRow] = wv.z;
        Bs[loadCol+3][loadRow] = wv.w;
        __syncthreads();
        #pragma unroll
        for (int kk = 0; kk < 8; kk++) {
            float ra[8], rb[8];
            #pragma unroll
            for (int i = 0; i < 8; i++) ra[i] = As[kk][ty * 8 + i];
            #pragma unroll
            for (int j = 0; j < 8; j++) rb[j] = Bs[kk][tx * 8 + j];
            #pragma unroll
            for (int i = 0; i < 8; i++)
                #pragma unroll
                for (int j = 0; j < 8; j++) acc[i][j] += ra[i] * rb[j];
        }
        __syncthreads();
    }

    #pragma unroll
    for (int i = 0; i < 8; i++) {
        int row = bm * 128 + ty * 8 + i;
        #pragma unroll
        for (int j = 0; j < 8; j++) {
            int col = bn * 128 + tx * 8 + j;
            float v = acc[i][j] + bias[col];
            if (EPI == 1) v = 1.f / (1.f + expf(-v));
            if (EPI == 2) v += res[(size_t)row * N + col];
            C[(size_t)row * N + col] = v;
        }
    }
}

// ---------------- scan phase 1: per-chunk affine aggregates -----------------
__global__ __launch_bounds__(Nn) void scan1_kernel(const unsigned char* __restrict__ reset)
{
    int blk = blockIdx.x;                 // b*H*NCH
    int c  = blk % NCH;
    int bh = blk / NCH;                   // b*H + h
    int hh = bh % Hh;
    int b  = bh / Hh;
    int n  = threadIdx.x;
    __shared__ float sd[CHUNK];
    int l0 = c * CHUNK;
    for (int i = n; i < CHUNK; i += Nn) {
        int l = l0 + i;
        float dd = g_delta[(size_t)(b * Ll + l) * Hh + hh];
        if (reset[b * Ll + l]) dd = 0.f;
        sd[i] = dd;
    }
    __syncthreads();
    float A = 1.f, Bc = 0.f;
    const size_t base = ((size_t)(b * Ll + l0) * Hh + hh) * 2 * Nn + n;
    #pragma unroll 4
    for (int i = 0; i < CHUNK; i++) {
        float dd = sd[i];
        float bt = g_param[base + (size_t)i * Hh * 2 * Nn];
        Bc = dd * Bc + bt;
        A *= dd;
    }
    g_Bagg[((size_t)bh * NCH + c) * Nn + n] = Bc;
    if (n == 0) g_Aagg[(size_t)bh * NCH + c] = A;
}

// ---------------- scan phase 2: scan over chunk aggregates ------------------
__global__ __launch_bounds__(Nn) void scan2_kernel(const float* __restrict__ state)
{
    int bh = blockIdx.x;                  // b*H + h
    int n  = threadIdx.x;
    float h = state[(size_t)bh * Nn + n];
    for (int c = 0; c < NCH; c++) {
        g_entry[((size_t)bh * NCH + c) * Nn + n] = h;
        h = g_Aagg[(size_t)bh * NCH + c] * h + g_Bagg[((size_t)bh * NCH + c) * Nn + n];
    }
}

// ---------------- scan phase 3: replay, write ssm_out = C_t * h -------------
__global__ __launch_bounds__(Nn) void scan3_kernel(
    const unsigned char* __restrict__ reset, float* __restrict__ new_state)
{
    int blk = blockIdx.x;
    int c  = blk % NCH;
    int bh = blk / NCH;
    int hh = bh % Hh;
    int b  = bh / Hh;
    int n  = threadIdx.x;
    __shared__ float sd[CHUNK];
    int l0 = c * CHUNK;
    for (int i = n; i < CHUNK; i += Nn) {
        int l = l0 + i;
        float dd = g_delta[(size_t)(b * Ll + l) * Hh + hh];
        if (reset[b * Ll + l]) dd = 0.f;
        sd[i] = dd;
    }
    __syncthreads();
    float h = g_entry[((size_t)bh * NCH + c) * Nn + n];
    const size_t base = ((size_t)(b * Ll + l0) * Hh + hh) * 2 * Nn + n;
    #pragma unroll 4
    for (int i = 0; i < CHUNK; i++) {
        float dd = sd[i];
        float bt = g_param[base + (size_t)i * Hh * 2 * Nn];
        h = dd * h + bt;
        float ct = g_param[base + (size_t)i * Hh * 2 * Nn + Nn];
        g_ssm[(size_t)(b * Ll + l0 + i) * Dd + hh * Nn + n] = ct * h;
    }
    if (c == NCH - 1) new_state[(size_t)bh * Nn + n] = h;
}

// ---------------- kernel: mixed = gate*ssm + (1-gate)*xnorm; rmsnorm --------
__global__ __launch_bounds__(256) void mixed_norm_kernel(const float* __restrict__ extra_w)
{
    int row = blockIdx.x;
    int tid = threadIdx.x;
    int lane = tid & 31, w = tid >> 5;
    __shared__ float ms[Dd];
    __shared__ float red[8];
    size_t off = (size_t)row * Dd;
    float ss = 0.f;
    for (int k = tid; k < Dd; k += 256) {
        float g = g_gate[off + k];
        float m = g * g_ssm[off + k] + (1.f - g) * g_xnorm[off + k];
        ms[k] = m;
        ss += m * m;
    }
    #pragma unroll
    for (int o = 16; o; o >>= 1) ss += __shfl_xor_sync(0xffffffffu, ss, o);
    if (lane == 0) red[w] = ss;
    __syncthreads();
    float tot = red[0]+red[1]+red[2]+red[3]+red[4]+red[5]+red[6]+red[7];
    float rstd = rsqrtf(tot / (float)Dd + EPSC);
    for (int k = tid; k < Dd; k += 256)
        g_mixn[off + k] = extra_w[k] * ms[k] * rstd;
}

// ---------------------------------------------------------------------------
extern "C" void kernel_launch(void* const* d_in, const int* in_sizes, int n_in,
                              void* d_out, int out_size)
{
    const float* x        = (const float*)d_in[0];
    const float* state    = (const float*)d_in[1];
    const unsigned char* reset = (const unsigned char*)d_in[2];
    const float* norm_w   = (const float*)d_in[3];
    const float* dt_W     = (const float*)d_in[4];
    const float* dt_b     = (const float*)d_in[5];
    const float* pp_W     = (const float*)d_in[6];
    const float* pp_b     = (const float*)d_in[7];
    const float* conv_w   = (const float*)d_in[8];
    const float* conv_b   = (const float*)d_in[9];
    const float* gate_W   = (const float*)d_in[10];
    const float* gate_b   = (const float*)d_in[11];
    const float* out_W    = (const float*)d_in[12];
    const float* out_b    = (const float*)d_in[13];
    const float* extra_w  = (const float*)d_in[14];

    float* y_out = (float*)d_out;                              // [B*L*D]
    float* ns_out = (float*)d_out + (size_t)Bb * Ll * Dd;      // [B*H*N]

    float *xnorm, *param, *xconv, *gate, *mixn;
    cudaGetSymbolAddress((void**)&xnorm, g_xnorm);
    cudaGetSymbolAddress((void**)&param, g_param);
    cudaGetSymbolAddress((void**)&xconv, g_xconv);
    cudaGetSymbolAddress((void**)&gate,  g_gate);
    cudaGetSymbolAddress((void**)&mixn,  g_mixn);

    const int M = Bb * Ll;                // 16384

    // 1. rmsnorm + dt head -> g_xnorm, g_delta
    rmsnorm_dt_kernel<<<M, 256>>>(x, norm_w, dt_W, dt_b);

    // 2. param GEMM: (16384,1024) x (2048,1024)^T -> g_param
    sgemm_k<0><<<dim3(2 * Hh * Nn / 128, M / 128), 256>>>(
        xnorm, pp_W, pp_b, nullptr, param, M, 2 * Hh * Nn, Dd);

    // 3. conv + silu -> g_xconv
    conv_kernel<<<(Bb * Ll * Dd) / 256, 256>>>(conv_w, conv_b);

    // 4. gate GEMM + sigmoid -> g_gate
    sgemm_k<1><<<dim3(Dd / 128, M / 128), 256>>>(
        xconv, gate_W, gate_b, nullptr, gate, M, Dd, Dd);

    // 5. chunked scan -> g_ssm, new_state
    scan1_kernel<<<Bb * Hh * NCH, Nn>>>(reset);
    scan2_kernel<<<Bb * Hh, Nn>>>(state);
    scan3_kernel<<<Bb * Hh * NCH, Nn>>>(reset, ns_out);

    // 6. mixed + rmsnorm -> g_mixn
    mixed_norm_kernel<<<M, 256>>>(extra_w);

    // 7. out GEMM + bias + residual -> y
    sgemm_k<2><<<dim3(Dd / 128, M / 128), 256>>>(
        mixn, out_W, out_b, x, y_out, M, Dd, Dd);
}

// round 5
// speedup vs baseline: 2.8759x; 2.8759x over previous
#include <cuda_runtime.h>
#include <cuda_bf16.h>
#include <stdint.h>
#include <math.h>

#define Bb 2
#define Ll 8192
#define Dd 1024
#define Hh 16
#define Nn 64
#define CHUNK 128
#define NCH (Ll / CHUNK)   // 64
#define DT_MIN 1e-4f
#define DT_MAX 0.1f
#define EPSC 1e-6f

#define Mrows (Bb * Ll)          // 16384
#define PPN   (2 * Hh * Nn)      // 2048

// GEMM tiling (HMMA mma.sync path — tcgen05 unavailable: harness PTX targets sm_103 base)
#define TM 128
#define TN 128
#define KC 64                    // bf16 per K chunk = 128 B/row (SW128 atom)
#define NKC (Dd / KC)            // 16
#define STG 65536                // Ah/Al/Wh/Wl tiles, 16 KB each
#define GSMEM (2 * STG)          // 131072

// ---------------- scratch (static __device__, no allocation) ----------------
__device__ float g_xnorm[(size_t)Mrows * Dd];
__device__ float g_param[(size_t)Mrows * PPN];
__device__ float g_delta[(size_t)Mrows * Hh];
__device__ float g_gate [(size_t)Mrows * Dd];
__device__ float g_ssm  [(size_t)Mrows * Dd];
__device__ float g_Aagg [(size_t)Bb * Hh * NCH];
__device__ float g_Bagg [(size_t)Bb * Hh * NCH * Nn];
__device__ float g_entry[(size_t)Bb * Hh * NCH * Nn];

// bf16 hi/lo split operands
__device__ __nv_bfloat16 g_xnh[(size_t)Mrows * Dd];
__device__ __nv_bfloat16 g_xnl[(size_t)Mrows * Dd];
__device__ __nv_bfloat16 g_xch[(size_t)Mrows * Dd];
__device__ __nv_bfloat16 g_xcl[(size_t)Mrows * Dd];
__device__ __nv_bfloat16 g_mxh[(size_t)Mrows * Dd];
__device__ __nv_bfloat16 g_mxl[(size_t)Mrows * Dd];
__device__ __nv_bfloat16 g_wpph[(size_t)PPN * Dd];
__device__ __nv_bfloat16 g_wppl[(size_t)PPN * Dd];
__device__ __nv_bfloat16 g_wgh[(size_t)Dd * Dd];
__device__ __nv_bfloat16 g_wgl[(size_t)Dd * Dd];
__device__ __nv_bfloat16 g_woh[(size_t)Dd * Dd];
__device__ __nv_bfloat16 g_wol[(size_t)Dd * Dd];

__device__ __forceinline__ float sigmoidf_(float v) { return 1.f / (1.f + expf(-v)); }

__device__ __forceinline__ void split_bf16(float v, __nv_bfloat16* hi, __nv_bfloat16* lo) {
    __nv_bfloat16 h = __float2bfloat16(v);
    *hi = h;
    *lo = __float2bfloat16(v - __bfloat162float(h));
}

// ---------------- PTX helpers (family-stable only) ----------------
__device__ __forceinline__ uint32_t smem_u32(const void* p) {
    uint32_t a;
    asm("{ .reg .u64 t; cvta.to.shared.u64 t, %1; cvt.u32.u64 %0, t; }" : "=r"(a) : "l"(p));
    return a;
}
__device__ __forceinline__ uint32_t sw128(uint32_t b) { return b ^ ((b >> 3) & 0x70); }

__device__ __forceinline__ void cp_async16(uint32_t saddr, const void* gaddr) {
    asm volatile("cp.async.cg.shared.global [%0], [%1], 16;\n" :: "r"(saddr), "l"(gaddr));
}
__device__ __forceinline__ void ldm_x4(uint32_t* r, uint32_t a) {
    asm volatile("ldmatrix.sync.aligned.m8n8.x4.shared.b16 {%0,%1,%2,%3}, [%4];"
        : "=r"(r[0]), "=r"(r[1]), "=r"(r[2]), "=r"(r[3]) : "r"(a));
}
__device__ __forceinline__ void mma_bf16(float* d, const uint32_t* a, const uint32_t* b) {
    asm volatile(
        "mma.sync.aligned.m16n8k16.row.col.f32.bf16.bf16.f32 "
        "{%0,%1,%2,%3}, {%4,%5,%6,%7}, {%8,%9}, {%0,%1,%2,%3};"
        : "+f"(d[0]), "+f"(d[1]), "+f"(d[2]), "+f"(d[3])
        : "r"(a[0]), "r"(a[1]), "r"(a[2]), "r"(a[3]), "r"(b[0]), "r"(b[1]));
}

// ---------------- HMMA split-bf16 GEMM: C = A * W^T + bias ------------------
// EPI: 0 = bias, 1 = sigmoid(bias+..), 2 = + residual
template<int EPI>
__global__ void __launch_bounds__(256, 1) hmma_gemm(
    const __nv_bfloat16* __restrict__ Ah, const __nv_bfloat16* __restrict__ Al,
    const __nv_bfloat16* __restrict__ Wh, const __nv_bfloat16* __restrict__ Wl,
    const float* __restrict__ bias, const float* __restrict__ res,
    float* __restrict__ C, int N, int K)
{
    extern __shared__ __align__(1024) char smem[];
    const uint32_t sbase = smem_u32(smem);
    const int tid = threadIdx.x, lane = tid & 31, wid = tid >> 5;
    const int bm = blockIdx.y, bn = blockIdx.x;
    const int m0 = (wid >> 2) * 64, n0 = (wid & 3) * 32;

    float acc[4][4][4];
    #pragma unroll
    for (int i = 0; i < 4; i++)
        #pragma unroll
        for (int j = 0; j < 4; j++)
            #pragma unroll
            for (int q = 0; q < 4; q++) acc[i][j][q] = 0.f;

    // ---- async load of one K-chunk (Ah/Al/Wh/Wl tiles, 16 KB each) ----
    #define ISSUE(cc) do {                                                    \
        uint32_t st_ = sbase + ((cc) & 1) * STG;                              \
        int kc0_ = (cc) * KC;                                                 \
        _Pragma("unroll")                                                     \
        for (int i_ = 0; i_ < 4; i_++) {                                      \
            int u_ = tid + 256 * i_;                                          \
            int r_ = u_ >> 3, sg_ = u_ & 7;                                   \
            uint32_t so_ = sw128((uint32_t)(r_ * 128 + sg_ * 16));            \
            size_t goA_ = (size_t)(bm * TM + r_) * K + kc0_ + sg_ * 8;        \
            size_t goW_ = (size_t)(bn * TN + r_) * K + kc0_ + sg_ * 8;        \
            cp_async16(st_ + so_,         Ah + goA_);                         \
            cp_async16(st_ + 16384 + so_, Al + goA_);                         \
            cp_async16(st_ + 32768 + so_, Wh + goW_);                         \
            cp_async16(st_ + 49152 + so_, Wl + goW_);                         \
        }                                                                     \
        asm volatile("cp.async.commit_group;\n" ::: "memory");                \
    } while (0)

    ISSUE(0);
    for (int c = 0; c < NKC; ++c) {
        if (c + 1 < NKC) {
            ISSUE(c + 1);
            asm volatile("cp.async.wait_group 1;\n" ::: "memory");
        } else {
            asm volatile("cp.async.wait_group 0;\n" ::: "memory");
        }
        __syncthreads();

        const uint32_t st = sbase + (c & 1) * STG;
        #pragma unroll
        for (int kk = 0; kk < 4; kk++) {
            uint32_t aH[4][4], aL[4][4], bH[4][2], bL[4][2];
            // A fragment addresses: lanes 0-15 rows, lanes 16-31 k+8
            const int arow = lane & 15;
            const int acb = kk * 32 + ((lane >> 4) & 1) * 16;
            #pragma unroll
            for (int mt = 0; mt < 4; mt++) {
                uint32_t off = sw128((uint32_t)((m0 + mt * 16 + arow) * 128 + acb));
                ldm_x4(aH[mt], st + off);
                ldm_x4(aL[mt], st + 16384 + off);
            }
            // B fragments: W rows are n, cols are k (row.col mma wants exactly this)
            const int brow = (lane & 7) + ((lane >> 4) & 1) * 8;
            const int bcb = kk * 32 + ((lane >> 3) & 1) * 16;
            #pragma unroll
            for (int t2 = 0; t2 < 2; t2++) {
                uint32_t off = sw128((uint32_t)((n0 + t2 * 16 + brow) * 128 + bcb));
                uint32_t tmp[4];
                ldm_x4(tmp, st + 32768 + off);
                bH[t2 * 2][0] = tmp[0]; bH[t2 * 2][1] = tmp[1];
                bH[t2 * 2 + 1][0] = tmp[2]; bH[t2 * 2 + 1][1] = tmp[3];
                ldm_x4(tmp, st + 49152 + off);
                bL[t2 * 2][0] = tmp[0]; bL[t2 * 2][1] = tmp[1];
                bL[t2 * 2 + 1][0] = tmp[2]; bL[t2 * 2 + 1][1] = tmp[3];
            }
            #pragma unroll
            for (int mt = 0; mt < 4; mt++)
                #pragma unroll
                for (int nt = 0; nt < 4; nt++) {
                    mma_bf16(acc[mt][nt], aH[mt], bH[nt]);
                    mma_bf16(acc[mt][nt], aH[mt], bL[nt]);
                    mma_bf16(acc[mt][nt], aL[mt], bH[nt]);
                }
        }
        __syncthreads();
    }
    #undef ISSUE

    // ---- epilogue ----
    #pragma unroll
    for (int mt = 0; mt < 4; mt++) {
        const int row = bm * TM + m0 + mt * 16 + (lane >> 2);
        #pragma unroll
        for (int nt = 0; nt < 4; nt++) {
            const int col = bn * TN + n0 + nt * 8 + (lane & 3) * 2;
            float b0 = bias[col], b1 = bias[col + 1];
            float v0 = acc[mt][nt][0] + b0, v1 = acc[mt][nt][1] + b1;
            float v2 = acc[mt][nt][2] + b0, v3 = acc[mt][nt][3] + b1;
            if (EPI == 1) {
                v0 = 1.f / (1.f + expf(-v0)); v1 = 1.f / (1.f + expf(-v1));
                v2 = 1.f / (1.f + expf(-v2)); v3 = 1.f / (1.f + expf(-v3));
            }
            if (EPI == 2) {
                v0 += res[(size_t)row * N + col];       v1 += res[(size_t)row * N + col + 1];
                v2 += res[(size_t)(row + 8) * N + col]; v3 += res[(size_t)(row + 8) * N + col + 1];
            }
            *(float2*)(C + (size_t)row * N + col)       = make_float2(v0, v1);
            *(float2*)(C + (size_t)(row + 8) * N + col) = make_float2(v2, v3);
        }
    }
}

// ---------------- kernel: weight fp32 -> bf16 hi/lo ----------------
__global__ __launch_bounds__(256) void wcvt_kernel(
    const float* __restrict__ ppW, const float* __restrict__ gW, const float* __restrict__ oW)
{
    size_t idx = (size_t)blockIdx.x * 256 + threadIdx.x;
    const size_t n_pp = (size_t)PPN * Dd;
    const size_t n_d2 = (size_t)Dd * Dd;
    float v; __nv_bfloat16 *dh, *dl; size_t j;
    if (idx < n_pp)                { j = idx;                v = ppW[j]; dh = g_wpph; dl = g_wppl; }
    else if (idx < n_pp + n_d2)    { j = idx - n_pp;         v = gW[j];  dh = g_wgh;  dl = g_wgl;  }
    else                           { j = idx - n_pp - n_d2;  v = oW[j];  dh = g_woh;  dl = g_wol;  }
    split_bf16(v, &dh[j], &dl[j]);
}

// ---------------- kernel 1: rmsnorm + dt projection ----------------
__global__ __launch_bounds__(256) void rmsnorm_dt_kernel(
    const float* __restrict__ x, const float* __restrict__ norm_w,
    const float* __restrict__ dtW, const float* __restrict__ dtb)
{
    int row = blockIdx.x;
    int tid = threadIdx.x;
    int lane = tid & 31, w = tid >> 5;
    __shared__ float xs[Dd];
    __shared__ float red[8];

    const float* xr = x + (size_t)row * Dd;
    float ss = 0.f;
    for (int k = tid; k < Dd; k += 256) { float v = xr[k]; xs[k] = v; ss += v * v; }
    #pragma unroll
    for (int o = 16; o; o >>= 1) ss += __shfl_xor_sync(0xffffffffu, ss, o);
    if (lane == 0) red[w] = ss;
    __syncthreads();
    float tot = red[0]+red[1]+red[2]+red[3]+red[4]+red[5]+red[6]+red[7];
    float rstd = rsqrtf(tot / (float)Dd + EPSC);

    for (int k = tid; k < Dd; k += 256) {
        float v = xs[k] * norm_w[k] * rstd;
        xs[k] = v;
        size_t o = (size_t)row * Dd + k;
        g_xnorm[o] = v;
        split_bf16(v, &g_xnh[o], &g_xnl[o]);
    }
    __syncthreads();

    for (int hh = w; hh < Hh; hh += 8) {
        const float* wr = dtW + (size_t)hh * Dd;
        float s = 0.f;
        for (int k = lane; k < Dd; k += 32) s += xs[k] * wr[k];
        #pragma unroll
        for (int o = 16; o; o >>= 1) s += __shfl_xor_sync(0xffffffffu, s, o);
        if (lane == 0) {
            float dtr = s + dtb[hh];
            float dt = DT_MIN + sigmoidf_(dtr) * (DT_MAX - DT_MIN);
            g_delta[(size_t)row * Hh + hh] = expf(-dt);
        }
    }
}

// ---------------- kernel 2: depthwise causal conv + silu -> bf16 hi/lo ------
__global__ __launch_bounds__(256) void conv_kernel(
    const float* __restrict__ cw, const float* __restrict__ cb)
{
    size_t idx = (size_t)blockIdx.x * 256 + threadIdx.x;
    int d = (int)(idx & (Dd - 1));
    size_t bl = idx >> 10;
    int l = (int)(bl & (Ll - 1));
    float w0 = cw[d*4+0], w1 = cw[d*4+1], w2 = cw[d*4+2], w3 = cw[d*4+3];
    float acc = cb[d];
    if (l >= 3) acc += w0 * g_xnorm[(bl - 3) * Dd + d];
    if (l >= 2) acc += w1 * g_xnorm[(bl - 2) * Dd + d];
    if (l >= 1) acc += w2 * g_xnorm[(bl - 1) * Dd + d];
    acc += w3 * g_xnorm[bl * Dd + d];
    float s = acc / (1.f + expf(-acc));
    split_bf16(s, &g_xch[idx], &g_xcl[idx]);
}

// ---------------- scan phases ----------------
__global__ __launch_bounds__(Nn) void scan1_kernel(const unsigned char* __restrict__ reset)
{
    int blk = blockIdx.x;
    int c  = blk % NCH;
    int bh = blk / NCH;
    int hh = bh % Hh;
    int b  = bh / Hh;
    int n  = threadIdx.x;
    __shared__ float sd[CHUNK];
    int l0 = c * CHUNK;
    for (int i = n; i < CHUNK; i += Nn) {
        int l = l0 + i;
        float dd = g_delta[(size_t)(b * Ll + l) * Hh + hh];
        if (reset[b * Ll + l]) dd = 0.f;
        sd[i] = dd;
    }
    __syncthreads();
    float A = 1.f, Bc = 0.f;
    const size_t base = ((size_t)(b * Ll + l0) * Hh + hh) * 2 * Nn + n;
    #pragma unroll 4
    for (int i = 0; i < CHUNK; i++) {
        float dd = sd[i];
        float bt = g_param[base + (size_t)i * Hh * 2 * Nn];
        Bc = dd * Bc + bt;
        A *= dd;
    }
    g_Bagg[((size_t)bh * NCH + c) * Nn + n] = Bc;
    if (n == 0) g_Aagg[(size_t)bh * NCH + c] = A;
}

__global__ __launch_bounds__(Nn) void scan2_kernel(const float* __restrict__ state)
{
    int bh = blockIdx.x;
    int n  = threadIdx.x;
    float h = state[(size_t)bh * Nn + n];
    for (int c = 0; c < NCH; c++) {
        g_entry[((size_t)bh * NCH + c) * Nn + n] = h;
        h = g_Aagg[(size_t)bh * NCH + c] * h + g_Bagg[((size_t)bh * NCH + c) * Nn + n];
    }
}

__global__ __launch_bounds__(Nn) void scan3_kernel(
    const unsigned char* __restrict__ reset, float* __restrict__ new_state)
{
    int blk = blockIdx.x;
    int c  = blk % NCH;
    int bh = blk / NCH;
    int hh = bh % Hh;
    int b  = bh / Hh;
    int n  = threadIdx.x;
    __shared__ float sd[CHUNK];
    int l0 = c * CHUNK;
    for (int i = n; i < CHUNK; i += Nn) {
        int l = l0 + i;
        float dd = g_delta[(size_t)(b * Ll + l) * Hh + hh];
        if (reset[b * Ll + l]) dd = 0.f;
        sd[i] = dd;
    }
    __syncthreads();
    float h = g_entry[((size_t)bh * NCH + c) * Nn + n];
    const size_t base = ((size_t)(b * Ll + l0) * Hh + hh) * 2 * Nn + n;
    #pragma unroll 4
    for (int i = 0; i < CHUNK; i++) {
        float dd = sd[i];
        float bt = g_param[base + (size_t)i * Hh * 2 * Nn];
        h = dd * h + bt;
        float ct = g_param[base + (size_t)i * Hh * 2 * Nn + Nn];
        g_ssm[(size_t)(b * Ll + l0 + i) * Dd + hh * Nn + n] = ct * h;
    }
    if (c == NCH - 1) new_state[(size_t)bh * Nn + n] = h;
}

// ---------------- mixed + rmsnorm -> bf16 hi/lo ----------------
__global__ __launch_bounds__(256) void mixed_norm_kernel(const float* __restrict__ extra_w)
{
    int row = blockIdx.x;
    int tid = threadIdx.x;
    int lane = tid & 31, w = tid >> 5;
    __shared__ float ms[Dd];
    __shared__ float red[8];
    size_t off = (size_t)row * Dd;
    float ss = 0.f;
    for (int k = tid; k < Dd; k += 256) {
        float g = g_gate[off + k];
        float m = g * g_ssm[off + k] + (1.f - g) * g_xnorm[off + k];
        ms[k] = m;
        ss += m * m;
    }
    #pragma unroll
    for (int o = 16; o; o >>= 1) ss += __shfl_xor_sync(0xffffffffu, ss, o);
    if (lane == 0) red[w] = ss;
    __syncthreads();
    float tot = red[0]+red[1]+red[2]+red[3]+red[4]+red[5]+red[6]+red[7];
    float rstd = rsqrtf(tot / (float)Dd + EPSC);
    for (int k = tid; k < Dd; k += 256) {
        float v = extra_w[k] * ms[k] * rstd;
        split_bf16(v, &g_mxh[off + k], &g_mxl[off + k]);
    }
}

// ---------------------------------------------------------------------------
extern "C" void kernel_launch(void* const* d_in, const int* in_sizes, int n_in,
                              void* d_out, int out_size)
{
    const float* x        = (const float*)d_in[0];
    const float* state    = (const float*)d_in[1];
    const unsigned char* reset = (const unsigned char*)d_in[2];
    const float* norm_w   = (const float*)d_in[3];
    const float* dt_W     = (const float*)d_in[4];
    const float* dt_b     = (const float*)d_in[5];
    const float* pp_W     = (const float*)d_in[6];
    const float* pp_b     = (const float*)d_in[7];
    const float* conv_w   = (const float*)d_in[8];
    const float* conv_b   = (const float*)d_in[9];
    const float* gate_W   = (const float*)d_in[10];
    const float* gate_b   = (const float*)d_in[11];
    const float* out_W    = (const float*)d_in[12];
    const float* out_b    = (const float*)d_in[13];
    const float* extra_w  = (const float*)d_in[14];

    float* y_out = (float*)d_out;
    float* ns_out = (float*)d_out + (size_t)Mrows * Dd;

    float *param, *gate;
    __nv_bfloat16 *xnh, *xnl, *xch, *xcl, *mxh, *mxl, *wpph, *wppl, *wgh, *wgl, *woh, *wol;
    cudaGetSymbolAddress((void**)&param, g_param);
    cudaGetSymbolAddress((void**)&gate,  g_gate);
    cudaGetSymbolAddress((void**)&xnh, g_xnh);  cudaGetSymbolAddress((void**)&xnl, g_xnl);
    cudaGetSymbolAddress((void**)&xch, g_xch);  cudaGetSymbolAddress((void**)&xcl, g_xcl);
    cudaGetSymbolAddress((void**)&mxh, g_mxh);  cudaGetSymbolAddress((void**)&mxl, g_mxl);
    cudaGetSymbolAddress((void**)&wpph, g_wpph); cudaGetSymbolAddress((void**)&wppl, g_wppl);
    cudaGetSymbolAddress((void**)&wgh, g_wgh);  cudaGetSymbolAddress((void**)&wgl, g_wgl);
    cudaGetSymbolAddress((void**)&woh, g_woh);  cudaGetSymbolAddress((void**)&wol, g_wol);

    cudaFuncSetAttribute(hmma_gemm<0>, cudaFuncAttributeMaxDynamicSharedMemorySize, GSMEM);
    cudaFuncSetAttribute(hmma_gemm<1>, cudaFuncAttributeMaxDynamicSharedMemorySize, GSMEM);
    cudaFuncSetAttribute(hmma_gemm<2>, cudaFuncAttributeMaxDynamicSharedMemorySize, GSMEM);

    // 0. weights -> bf16 hi/lo
    wcvt_kernel<<<(PPN * Dd + 2 * Dd * Dd) / 256, 256>>>(pp_W, gate_W, out_W);

    // 1. rmsnorm + dt head
    rmsnorm_dt_kernel<<<Mrows, 256>>>(x, norm_w, dt_W, dt_b);

    // 2. param GEMM (16384 x 2048 x 1024)
    hmma_gemm<0><<<dim3(PPN / TN, Mrows / TM), 256, GSMEM>>>(
        xnh, xnl, wpph, wppl, pp_b, nullptr, param, PPN, Dd);

    // 3. conv + silu
    conv_kernel<<<((size_t)Mrows * Dd) / 256, 256>>>(conv_w, conv_b);

    // 4. gate GEMM + sigmoid
    hmma_gemm<1><<<dim3(Dd / TN, Mrows / TM), 256, GSMEM>>>(
        xch, xcl, wgh, wgl, gate_b, nullptr, gate, Dd, Dd);

    // 5. chunked scan
    scan1_kernel<<<Bb * Hh * NCH, Nn>>>(reset);
    scan2_kernel<<<Bb * Hh, Nn>>>(state);
    scan3_kernel<<<Bb * Hh * NCH, Nn>>>(reset, ns_out);

    // 6. mixed + rmsnorm
    mixed_norm_kernel<<<Mrows, 256>>>(extra_w);

    // 7. out GEMM + bias + residual
    hmma_gemm<2><<<dim3(Dd / TN, Mrows / TM), 256, GSMEM>>>(
        mxh, mxl, woh, wol, out_b, x, y_out, Dd, Dd);
}

// round 6
// speedup vs baseline: 2.9395x; 1.0221x over previous
#include <cuda_runtime.h>
#include <cuda_bf16.h>
#include <stdint.h>
#include <math.h>

#define Bb 2
#define Ll 8192
#define Dd 1024
#define Hh 16
#define Nn 64
#define CHUNK 128
#define NCH (Ll / CHUNK)   // 64
#define DT_MIN 1e-4f
#define DT_MAX 0.1f
#define EPSC 1e-6f

#define Mrows (Bb * Ll)          // 16384
#define PPN   (2 * Hh * Nn)      // 2048

// GEMM tiling (HMMA mma.sync path — tcgen05 unavailable: harness PTX targets sm_103 base)
#define TM 128
#define TN 128
#define KC 64                    // bf16 per K chunk = 128 B/row (SW128 atom)
#define NKC (Dd / KC)            // 16
#define STG 65536                // Ah/Al/Wh/Wl tiles, 16 KB each
#define NSTAGE 3
#define GSMEM (NSTAGE * STG)     // 196608

// conv tiling
#define CLROWS 32                // l rows per block

// ---------------- scratch (static __device__, no allocation) ----------------
__device__ float g_xnorm[(size_t)Mrows * Dd];
__device__ float g_param[(size_t)Mrows * PPN];
__device__ float g_delta[(size_t)Mrows * Hh];
__device__ float g_gate [(size_t)Mrows * Dd];
__device__ float g_ssm  [(size_t)Mrows * Dd];
__device__ float g_Aagg [(size_t)Bb * Hh * NCH];
__device__ float g_Bagg [(size_t)Bb * Hh * NCH * Nn];
__device__ float g_entry[(size_t)Bb * Hh * NCH * Nn];

// bf16 hi/lo split operands
__device__ __nv_bfloat16 g_xnh[(size_t)Mrows * Dd];
__device__ __nv_bfloat16 g_xnl[(size_t)Mrows * Dd];
__device__ __nv_bfloat16 g_xch[(size_t)Mrows * Dd];
__device__ __nv_bfloat16 g_xcl[(size_t)Mrows * Dd];
__device__ __nv_bfloat16 g_mxh[(size_t)Mrows * Dd];
__device__ __nv_bfloat16 g_mxl[(size_t)Mrows * Dd];
__device__ __nv_bfloat16 g_wpph[(size_t)PPN * Dd];
__device__ __nv_bfloat16 g_wppl[(size_t)PPN * Dd];
__device__ __nv_bfloat16 g_wgh[(size_t)Dd * Dd];
__device__ __nv_bfloat16 g_wgl[(size_t)Dd * Dd];
__device__ __nv_bfloat16 g_woh[(size_t)Dd * Dd];
__device__ __nv_bfloat16 g_wol[(size_t)Dd * Dd];

__device__ __forceinline__ float sigmoidf_(float v) { return 1.f / (1.f + expf(-v)); }

__device__ __forceinline__ void split_bf16(float v, __nv_bfloat16* hi, __nv_bfloat16* lo) {
    __nv_bfloat16 h = __float2bfloat16(v);
    *hi = h;
    *lo = __float2bfloat16(v - __bfloat162float(h));
}

// ---------------- PTX helpers (family-stable only) ----------------
__device__ __forceinline__ uint32_t smem_u32(const void* p) {
    uint32_t a;
    asm("{ .reg .u64 t; cvta.to.shared.u64 t, %1; cvt.u32.u64 %0, t; }" : "=r"(a) : "l"(p));
    return a;
}
__device__ __forceinline__ uint32_t sw128(uint32_t b) { return b ^ ((b >> 3) & 0x70); }

__device__ __forceinline__ void cp_async16(uint32_t saddr, const void* gaddr) {
    asm volatile("cp.async.cg.shared.global [%0], [%1], 16;\n" :: "r"(saddr), "l"(gaddr));
}
__device__ __forceinline__ void ldm_x4(uint32_t* r, uint32_t a) {
    asm volatile("ldmatrix.sync.aligned.m8n8.x4.shared.b16 {%0,%1,%2,%3}, [%4];"
        : "=r"(r[0]), "=r"(r[1]), "=r"(r[2]), "=r"(r[3]) : "r"(a));
}
__device__ __forceinline__ void mma_bf16(float* d, const uint32_t* a, const uint32_t* b) {
    asm volatile(
        "mma.sync.aligned.m16n8k16.row.col.f32.bf16.bf16.f32 "
        "{%0,%1,%2,%3}, {%4,%5,%6,%7}, {%8,%9}, {%0,%1,%2,%3};"
        : "+f"(d[0]), "+f"(d[1]), "+f"(d[2]), "+f"(d[3])
        : "r"(a[0]), "r"(a[1]), "r"(a[2]), "r"(a[3]), "r"(b[0]), "r"(b[1]));
}

// ---------------- HMMA split-bf16 GEMM: C = A * W^T + bias ------------------
// EPI: 0 = bias, 1 = sigmoid(bias+..), 2 = + residual
template<int EPI>
__global__ void __launch_bounds__(256, 1) hmma_gemm(
    const __nv_bfloat16* __restrict__ Ah, const __nv_bfloat16* __restrict__ Al,
    const __nv_bfloat16* __restrict__ Wh, const __nv_bfloat16* __restrict__ Wl,
    const float* __restrict__ bias, const float* __restrict__ res,
    float* __restrict__ C, int N, int K)
{
    extern __shared__ __align__(1024) char smem[];
    const uint32_t sbase = smem_u32(smem);
    const int tid = threadIdx.x, lane = tid & 31, wid = tid >> 5;
    const int bm = blockIdx.y, bn = blockIdx.x;
    const int m0 = (wid >> 2) * 64, n0 = (wid & 3) * 32;

    float acc[4][4][4];
    #pragma unroll
    for (int i = 0; i < 4; i++)
        #pragma unroll
        for (int j = 0; j < 4; j++)
            #pragma unroll
            for (int q = 0; q < 4; q++) acc[i][j][q] = 0.f;

    // ---- async load of one K-chunk (Ah/Al/Wh/Wl tiles, 16 KB each) ----
    #define ISSUE(cc) do {                                                    \
        uint32_t st_ = sbase + ((cc) % NSTAGE) * STG;                         \
        int kc0_ = (cc) * KC;                                                 \
        _Pragma("unroll")                                                     \
        for (int i_ = 0; i_ < 4; i_++) {                                      \
            int u_ = tid + 256 * i_;                                          \
            int r_ = u_ >> 3, sg_ = u_ & 7;                                   \
            uint32_t so_ = sw128((uint32_t)(r_ * 128 + sg_ * 16));            \
            size_t goA_ = (size_t)(bm * TM + r_) * K + kc0_ + sg_ * 8;        \
            size_t goW_ = (size_t)(bn * TN + r_) * K + kc0_ + sg_ * 8;        \
            cp_async16(st_ + so_,         Ah + goA_);                         \
            cp_async16(st_ + 16384 + so_, Al + goA_);                         \
            cp_async16(st_ + 32768 + so_, Wh + goW_);                         \
            cp_async16(st_ + 49152 + so_, Wl + goW_);                         \
        }                                                                     \
        asm volatile("cp.async.commit_group;\n" ::: "memory");                \
    } while (0)

    ISSUE(0);
    ISSUE(1);
    for (int c = 0; c < NKC; ++c) {
        // prefetch depth 2: issue chunk c+2 (its stage was last read at chunk c-1,
        // protected by the bottom __syncthreads)
        if (c + 2 < NKC) {
            ISSUE(c + 2);
            asm volatile("cp.async.wait_group 2;\n" ::: "memory");
        } else if (c + 1 < NKC) {
            asm volatile("cp.async.wait_group 1;\n" ::: "memory");
        } else {
            asm volatile("cp.async.wait_group 0;\n" ::: "memory");
        }
        __syncthreads();

        const uint32_t st = sbase + (c % NSTAGE) * STG;
        #pragma unroll
        for (int kk = 0; kk < 4; kk++) {
            uint32_t aH[4][4], aL[4][4], bH[4][2], bL[4][2];
            const int arow = lane & 15;
            const int acb = kk * 32 + ((lane >> 4) & 1) * 16;
            #pragma unroll
            for (int mt = 0; mt < 4; mt++) {
                uint32_t off = sw128((uint32_t)((m0 + mt * 16 + arow) * 128 + acb));
                ldm_x4(aH[mt], st + off);
                ldm_x4(aL[mt], st + 16384 + off);
            }
            const int brow = (lane & 7) + ((lane >> 4) & 1) * 8;
            const int bcb = kk * 32 + ((lane >> 3) & 1) * 16;
            #pragma unroll
            for (int t2 = 0; t2 < 2; t2++) {
                uint32_t off = sw128((uint32_t)((n0 + t2 * 16 + brow) * 128 + bcb));
                uint32_t tmp[4];
                ldm_x4(tmp, st + 32768 + off);
                bH[t2 * 2][0] = tmp[0]; bH[t2 * 2][1] = tmp[1];
                bH[t2 * 2 + 1][0] = tmp[2]; bH[t2 * 2 + 1][1] = tmp[3];
                ldm_x4(tmp, st + 49152 + off);
                bL[t2 * 2][0] = tmp[0]; bL[t2 * 2][1] = tmp[1];
                bL[t2 * 2 + 1][0] = tmp[2]; bL[t2 * 2 + 1][1] = tmp[3];
            }
            #pragma unroll
            for (int mt = 0; mt < 4; mt++)
                #pragma unroll
                for (int nt = 0; nt < 4; nt++) {
                    mma_bf16(acc[mt][nt], aH[mt], bH[nt]);
                    mma_bf16(acc[mt][nt], aH[mt], bL[nt]);
                    mma_bf16(acc[mt][nt], aL[mt], bH[nt]);
                }
        }
        __syncthreads();
    }
    #undef ISSUE

    // ---- epilogue ----
    #pragma unroll
    for (int mt = 0; mt < 4; mt++) {
        const int row = bm * TM + m0 + mt * 16 + (lane >> 2);
        #pragma unroll
        for (int nt = 0; nt < 4; nt++) {
            const int col = bn * TN + n0 + nt * 8 + (lane & 3) * 2;
            float b0 = bias[col], b1 = bias[col + 1];
            float v0 = acc[mt][nt][0] + b0, v1 = acc[mt][nt][1] + b1;
            float v2 = acc[mt][nt][2] + b0, v3 = acc[mt][nt][3] + b1;
            if (EPI == 1) {
                v0 = 1.f / (1.f + expf(-v0)); v1 = 1.f / (1.f + expf(-v1));
                v2 = 1.f / (1.f + expf(-v2)); v3 = 1.f / (1.f + expf(-v3));
            }
            if (EPI == 2) {
                v0 += res[(size_t)row * N + col];       v1 += res[(size_t)row * N + col + 1];
                v2 += res[(size_t)(row + 8) * N + col]; v3 += res[(size_t)(row + 8) * N + col + 1];
            }
            *(float2*)(C + (size_t)row * N + col)       = make_float2(v0, v1);
            *(float2*)(C + (size_t)(row + 8) * N + col) = make_float2(v2, v3);
        }
    }
}

// ---------------- kernel: weight fp32 -> bf16 hi/lo ----------------
__global__ __launch_bounds__(256) void wcvt_kernel(
    const float* __restrict__ ppW, const float* __restrict__ gW, const float* __restrict__ oW)
{
    size_t idx = (size_t)blockIdx.x * 256 + threadIdx.x;
    const size_t n_pp = (size_t)PPN * Dd;
    const size_t n_d2 = (size_t)Dd * Dd;
    float v; __nv_bfloat16 *dh, *dl; size_t j;
    if (idx < n_pp)                { j = idx;                v = ppW[j]; dh = g_wpph; dl = g_wppl; }
    else if (idx < n_pp + n_d2)    { j = idx - n_pp;         v = gW[j];  dh = g_wgh;  dl = g_wgl;  }
    else                           { j = idx - n_pp - n_d2;  v = oW[j];  dh = g_woh;  dl = g_wol;  }
    split_bf16(v, &dh[j], &dl[j]);
}

// ---------------- kernel 1: rmsnorm + dt projection ----------------
__global__ __launch_bounds__(256) void rmsnorm_dt_kernel(
    const float* __restrict__ x, const float* __restrict__ norm_w,
    const float* __restrict__ dtW, const float* __restrict__ dtb)
{
    int row = blockIdx.x;
    int tid = threadIdx.x;
    int lane = tid & 31, w = tid >> 5;
    __shared__ float xs[Dd];
    __shared__ float red[8];

    const float* xr = x + (size_t)row * Dd;
    float ss = 0.f;
    for (int k = tid; k < Dd; k += 256) { float v = xr[k]; xs[k] = v; ss += v * v; }
    #pragma unroll
    for (int o = 16; o; o >>= 1) ss += __shfl_xor_sync(0xffffffffu, ss, o);
    if (lane == 0) red[w] = ss;
    __syncthreads();
    float tot = red[0]+red[1]+red[2]+red[3]+red[4]+red[5]+red[6]+red[7];
    float rstd = rsqrtf(tot / (float)Dd + EPSC);

    for (int k = tid; k < Dd; k += 256) {
        float v = xs[k] * norm_w[k] * rstd;
        xs[k] = v;
        size_t o = (size_t)row * Dd + k;
        g_xnorm[o] = v;
        split_bf16(v, &g_xnh[o], &g_xnl[o]);
    }
    __syncthreads();

    for (int hh = w; hh < Hh; hh += 8) {
        const float* wr = dtW + (size_t)hh * Dd;
        float s = 0.f;
        for (int k = lane; k < Dd; k += 32) s += xs[k] * wr[k];
        #pragma unroll
        for (int o = 16; o; o >>= 1) s += __shfl_xor_sync(0xffffffffu, s, o);
        if (lane == 0) {
            float dtr = s + dtb[hh];
            float dt = DT_MIN + sigmoidf_(dtr) * (DT_MAX - DT_MIN);
            g_delta[(size_t)row * Hh + hh] = expf(-dt);
        }
    }
}

// ---------------- kernel 2: depthwise causal conv + silu (sliding window) ---
// block: 256 threads covering a 256-wide d-slice; iterates CLROWS l rows,
// carrying the 3-tap history in registers (1.19x reads vs 4x before).
__global__ __launch_bounds__(256) void conv_kernel(
    const float* __restrict__ cw, const float* __restrict__ cb)
{
    const int dblk = blockIdx.x & 3;                    // Dd/256 = 4
    const size_t bl0 = (size_t)(blockIdx.x >> 2) * CLROWS;
    const int d = dblk * 256 + threadIdx.x;
    const int l0 = (int)(bl0 & (Ll - 1));               // CLROWS divides Ll

    const float w0 = cw[d*4+0], w1 = cw[d*4+1], w2 = cw[d*4+2], w3 = cw[d*4+3];
    const float bias = cb[d];

    float xm3, xm2, xm1;
    if (l0 == 0) { xm3 = 0.f; xm2 = 0.f; xm1 = 0.f; }
    else {
        xm3 = g_xnorm[(bl0 - 3) * Dd + d];
        xm2 = g_xnorm[(bl0 - 2) * Dd + d];
        xm1 = g_xnorm[(bl0 - 1) * Dd + d];
    }
    #pragma unroll 4
    for (int i = 0; i < CLROWS; i++) {
        const size_t bl = bl0 + i;
        float xc = g_xnorm[bl * Dd + d];
        float acc = bias + w0 * xm3 + w1 * xm2 + w2 * xm1 + w3 * xc;
        float s = acc / (1.f + expf(-acc));
        split_bf16(s, &g_xch[bl * Dd + d], &g_xcl[bl * Dd + d]);
        xm3 = xm2; xm2 = xm1; xm1 = xc;
    }
}

// ---------------- scan phases ----------------
__global__ __launch_bounds__(Nn) void scan1_kernel(const unsigned char* __restrict__ reset)
{
    int blk = blockIdx.x;
    int c  = blk % NCH;
    int bh = blk / NCH;
    int hh = bh % Hh;
    int b  = bh / Hh;
    int n  = threadIdx.x;
    __shared__ float sd[CHUNK];
    int l0 = c * CHUNK;
    for (int i = n; i < CHUNK; i += Nn) {
        int l = l0 + i;
        float dd = g_delta[(size_t)(b * Ll + l) * Hh + hh];
        if (reset[b * Ll + l]) dd = 0.f;
        sd[i] = dd;
    }
    __syncthreads();
    float A = 1.f, Bc = 0.f;
    const size_t base = ((size_t)(b * Ll + l0) * Hh + hh) * 2 * Nn + n;
    #pragma unroll 4
    for (int i = 0; i < CHUNK; i++) {
        float dd = sd[i];
        float bt = g_param[base + (size_t)i * Hh * 2 * Nn];
        Bc = dd * Bc + bt;
        A *= dd;
    }
    g_Bagg[((size_t)bh * NCH + c) * Nn + n] = Bc;
    if (n == 0) g_Aagg[(size_t)bh * NCH + c] = A;
}

__global__ __launch_bounds__(Nn) void scan2_kernel(const float* __restrict__ state)
{
    int bh = blockIdx.x;
    int n  = threadIdx.x;
    float h = state[(size_t)bh * Nn + n];
    for (int c = 0; c < NCH; c++) {
        g_entry[((size_t)bh * NCH + c) * Nn + n] = h;
        h = g_Aagg[(size_t)bh * NCH + c] * h + g_Bagg[((size_t)bh * NCH + c) * Nn + n];
    }
}

__global__ __launch_bounds__(Nn) void scan3_kernel(
    const unsigned char* __restrict__ reset, float* __restrict__ new_state)
{
    int blk = blockIdx.x;
    int c  = blk % NCH;
    int bh = blk / NCH;
    int hh = bh % Hh;
    int b  = bh / Hh;
    int n  = threadIdx.x;
    __shared__ float sd[CHUNK];
    int l0 = c * CHUNK;
    for (int i = n; i < CHUNK; i += Nn) {
        int l = l0 + i;
        float dd = g_delta[(size_t)(b * Ll + l) * Hh + hh];
        if (reset[b * Ll + l]) dd = 0.f;
        sd[i] = dd;
    }
    __syncthreads();
    float h = g_entry[((size_t)bh * NCH + c) * Nn + n];
    const size_t base = ((size_t)(b * Ll + l0) * Hh + hh) * 2 * Nn + n;
    #pragma unroll 4
    for (int i = 0; i < CHUNK; i++) {
        float dd = sd[i];
        float bt = g_param[base + (size_t)i * Hh * 2 * Nn];
        h = dd * h + bt;
        float ct = g_param[base + (size_t)i * Hh * 2 * Nn + Nn];
        g_ssm[(size_t)(b * Ll + l0 + i) * Dd + hh * Nn + n] = ct * h;
    }
    if (c == NCH - 1) new_state[(size_t)bh * Nn + n] = h;
}

// ---------------- mixed + rmsnorm -> bf16 hi/lo ----------------
__global__ __launch_bounds__(256) void mixed_norm_kernel(const float* __restrict__ extra_w)
{
    int row = blockIdx.x;
    int tid = threadIdx.x;
    int lane = tid & 31, w = tid >> 5;
    __shared__ float ms[Dd];
    __shared__ float red[8];
    size_t off = (size_t)row * Dd;
    float ss = 0.f;
    for (int k = tid; k < Dd; k += 256) {
        float g = g_gate[off + k];
        float m = g * g_ssm[off + k] + (1.f - g) * g_xnorm[off + k];
        ms[k] = m;
        ss += m * m;
    }
    #pragma unroll
    for (int o = 16; o; o >>= 1) ss += __shfl_xor_sync(0xffffffffu, ss, o);
    if (lane == 0) red[w] = ss;
    __syncthreads();
    float tot = red[0]+red[1]+red[2]+red[3]+red[4]+red[5]+red[6]+red[7];
    float rstd = rsqrtf(tot / (float)Dd + EPSC);
    for (int k = tid; k < Dd; k += 256) {
        float v = extra_w[k] * ms[k] * rstd;
        split_bf16(v, &g_mxh[off + k], &g_mxl[off + k]);
    }
}

// ---------------------------------------------------------------------------
extern "C" void kernel_launch(void* const* d_in, const int* in_sizes, int n_in,
                              void* d_out, int out_size)
{
    const float* x        = (const float*)d_in[0];
    const float* state    = (const float*)d_in[1];
    const unsigned char* reset = (const unsigned char*)d_in[2];
    const float* norm_w   = (const float*)d_in[3];
    const float* dt_W     = (const float*)d_in[4];
    const float* dt_b     = (const float*)d_in[5];
    const float* pp_W     = (const float*)d_in[6];
    const float* pp_b     = (const float*)d_in[7];
    const float* conv_w   = (const float*)d_in[8];
    const float* conv_b   = (const float*)d_in[9];
    const float* gate_W   = (const float*)d_in[10];
    const float* gate_b   = (const float*)d_in[11];
    const float* out_W    = (const float*)d_in[12];
    const float* out_b    = (const float*)d_in[13];
    const float* extra_w  = (const float*)d_in[14];

    float* y_out = (float*)d_out;
    float* ns_out = (float*)d_out + (size_t)Mrows * Dd;

    float *param, *gate;
    __nv_bfloat16 *xnh, *xnl, *xch, *xcl, *mxh, *mxl, *wpph, *wppl, *wgh, *wgl, *woh, *wol;
    cudaGetSymbolAddress((void**)&param, g_param);
    cudaGetSymbolAddress((void**)&gate,  g_gate);
    cudaGetSymbolAddress((void**)&xnh, g_xnh);  cudaGetSymbolAddress((void**)&xnl, g_xnl);
    cudaGetSymbolAddress((void**)&xch, g_xch);  cudaGetSymbolAddress((void**)&xcl, g_xcl);
    cudaGetSymbolAddress((void**)&mxh, g_mxh);  cudaGetSymbolAddress((void**)&mxl, g_mxl);
    cudaGetSymbolAddress((void**)&wpph, g_wpph); cudaGetSymbolAddress((void**)&wppl, g_wppl);
    cudaGetSymbolAddress((void**)&wgh, g_wgh);  cudaGetSymbolAddress((void**)&wgl, g_wgl);
    cudaGetSymbolAddress((void**)&woh, g_woh);  cudaGetSymbolAddress((void**)&wol, g_wol);

    cudaFuncSetAttribute(hmma_gemm<0>, cudaFuncAttributeMaxDynamicSharedMemorySize, GSMEM);
    cudaFuncSetAttribute(hmma_gemm<1>, cudaFuncAttributeMaxDynamicSharedMemorySize, GSMEM);
    cudaFuncSetAttribute(hmma_gemm<2>, cudaFuncAttributeMaxDynamicSharedMemorySize, GSMEM);

    // 0. weights -> bf16 hi/lo
    wcvt_kernel<<<(PPN * Dd + 2 * Dd * Dd) / 256, 256>>>(pp_W, gate_W, out_W);

    // 1. rmsnorm + dt head
    rmsnorm_dt_kernel<<<Mrows, 256>>>(x, norm_w, dt_W, dt_b);

    // 2. param GEMM (16384 x 2048 x 1024)
    hmma_gemm<0><<<dim3(PPN / TN, Mrows / TM), 256, GSMEM>>>(
        xnh, xnl, wpph, wppl, pp_b, nullptr, param, PPN, Dd);

    // 3. conv + silu (sliding window)
    conv_kernel<<<(Mrows / CLROWS) * (Dd / 256), 256>>>(conv_w, conv_b);

    // 4. gate GEMM + sigmoid
    hmma_gemm<1><<<dim3(Dd / TN, Mrows / TM), 256, GSMEM>>>(
        xch, xcl, wgh, wgl, gate_b, nullptr, gate, Dd, Dd);

    // 5. chunked scan
    scan1_kernel<<<Bb * Hh * NCH, Nn>>>(reset);
    scan2_kernel<<<Bb * Hh, Nn>>>(state);
    scan3_kernel<<<Bb * Hh * NCH, Nn>>>(reset, ns_out);

    // 6. mixed + rmsnorm
    mixed_norm_kernel<<<Mrows, 256>>>(extra_w);

    // 7. out GEMM + bias + residual
    hmma_gemm<2><<<dim3(Dd / TN, Mrows / TM), 256, GSMEM>>>(
        mxh, mxl, woh, wol, out_b, x, y_out, Dd, Dd);
}